// round 15
// baseline (speedup 1.0000x reference)
#include <cuda_runtime.h>
#include <cstdint>

#define N_MODES 4
#define BATCH   1024
#define PH      128
#define PW      128
#define OBJ_H   2048
#define OBJ_W   2048

#define PATCHES_ELEMS (BATCH * PH * PW)   // 16,777,216
#define NORM_ELEMS    (OBJ_H * OBJ_W)     // 4,194,304
#define N_CHUNKS      (BATCH * (PH / 8))  // 16384 (8-row chunks)
#define PERSIST_GRID  1184                // 148 SMs x 8 resident 256-thr blocks

// ---------------------------------------------------------------------------
// Kernel 1: zero object_norm (best measured config: 4096 x 256, plain
// coalesced float4 stores).
// ---------------------------------------------------------------------------
__global__ void __launch_bounds__(256) bc_zero_norm(float4* __restrict__ norm4) {
    int i = blockIdx.x * 256 + threadIdx.x;            // NORM_ELEMS/4 threads
    norm4[i] = make_float4(0.f, 0.f, 0.f, 0.f);
}

// ---------------------------------------------------------------------------
// Kernel 2: PERSISTENT fused patch-norm + scatter-add + batch-crop.
// Grid = exactly one full wave (1184 blocks x 256 thr = 8 blocks/SM).
// Each block grid-strides over the 16384 8-row chunks; the per-chunk body is
// bit-identical to the proven R3 winner (1 row/warp, shuffle realign,
// streaming policy, aligned red.v4). Removes ~15k block launches and all
// wave-transition idle.
// ---------------------------------------------------------------------------
__global__ void __launch_bounds__(256) bc_main(
    const float*  __restrict__ obj,
    const float4* __restrict__ waves4,
    const int*    __restrict__ pos,
    float4*       __restrict__ patches4,
    float*        __restrict__ norm)
{
    const int t = threadIdx.x;
    const int r = t >> 5;                 // warp id = row within chunk
    const int g = t & 31;                 // lane = float4 group within row
    const size_t MS = (size_t)BATCH * PH * (PW / 4);

    for (int chunk = blockIdx.x; chunk < N_CHUNKS; chunk += PERSIST_GRID) {
        const int b  = chunk >> 4;            // patch index
        const int h0 = (chunk & 15) << 3;     // first row of this 8-row chunk
        const int h  = h0 + r;

        const int pr = __ldg(&pos[2 * b]);
        const int pc = __ldg(&pos[2 * b + 1]);
        const int s  = pc & 3;                // misalignment (uniform per block)
        const int A  = pc - s;                // 16B-aligned start column

        // ---- patch_norm = sum over 4 modes of waves^2 (streaming) ----
        const size_t pidx = ((size_t)b * PH + h) * (PW / 4) + g;

        float4 a0 = __ldcs(&waves4[pidx]);
        float4 a1 = __ldcs(&waves4[pidx + MS]);
        float4 a2 = __ldcs(&waves4[pidx + 2 * MS]);
        float4 a3 = __ldcs(&waves4[pidx + 3 * MS]);

        float4 nv;
        nv.x = a0.x*a0.x + a1.x*a1.x + a2.x*a2.x + a3.x*a3.x;
        nv.y = a0.y*a0.y + a1.y*a1.y + a2.y*a2.y + a3.y*a3.y;
        nv.z = a0.z*a0.z + a1.z*a1.z + a2.z*a2.z + a3.z*a3.z;
        nv.w = a0.w*a0.w + a1.w*a1.w + a2.w*a2.w + a3.w*a3.w;

        // ---- obj gather: ALIGNED float4 loads + shuffle realign ----
        const float4* orow4 = (const float4*)(obj + (size_t)(pr + h) * OBJ_W + A);
        float4 L = __ldg(&orow4[g]);
        float4 E = make_float4(0.f, 0.f, 0.f, 0.f);
        if (s && g == 31) E = __ldg(&orow4[32]);   // pc <= 1919 -> in-row

        float4 nxt;
        nxt.x = __shfl_down_sync(0xffffffffu, L.x, 1);
        nxt.y = __shfl_down_sync(0xffffffffu, L.y, 1);
        nxt.z = __shfl_down_sync(0xffffffffu, L.z, 1);
        nxt.w = __shfl_down_sync(0xffffffffu, L.w, 1);
        if (g == 31) nxt = E;

        float4 v;
        switch (s) {        // uniform branch (same s for whole block)
            case 0:  v = L; break;
            case 1:  v = make_float4(L.y, L.z, L.w, nxt.x); break;
            case 2:  v = make_float4(L.z, L.w, nxt.x, nxt.y); break;
            default: v = make_float4(L.w, nxt.x, nxt.y, nxt.z); break;
        }
        __stcs(&patches4[pidx], v);

        // ---- norm scatter: shuffle de-align + ALIGNED red.v4 ----
        float4 prev;
        prev.x = __shfl_up_sync(0xffffffffu, nv.x, 1);
        prev.y = __shfl_up_sync(0xffffffffu, nv.y, 1);
        prev.z = __shfl_up_sync(0xffffffffu, nv.z, 1);
        prev.w = __shfl_up_sync(0xffffffffu, nv.w, 1);
        if (g == 0) prev = make_float4(0.f, 0.f, 0.f, 0.f);

        float4 o;
        switch (s) {
            case 0:  o = nv; break;
            case 1:  o = make_float4(prev.w, nv.x, nv.y, nv.z); break;
            case 2:  o = make_float4(prev.z, prev.w, nv.x, nv.y); break;
            default: o = make_float4(prev.y, prev.z, prev.w, nv.x); break;
        }

        float* nrow = norm + (size_t)(pr + h) * OBJ_W;
        asm volatile("red.global.add.v4.f32 [%0], {%1, %2, %3, %4};"
                     :: "l"(nrow + A + 4 * g), "f"(o.x), "f"(o.y), "f"(o.z), "f"(o.w)
                     : "memory");

        if (s && g == 31) {
            float4 e;
            switch (s) {
                case 1:  e = make_float4(nv.w, 0.f, 0.f, 0.f); break;
                case 2:  e = make_float4(nv.z, nv.w, 0.f, 0.f); break;
                default: e = make_float4(nv.y, nv.z, nv.w, 0.f); break;
            }
            asm volatile("red.global.add.v4.f32 [%0], {%1, %2, %3, %4};"
                         :: "l"(nrow + A + 128), "f"(e.x), "f"(e.y), "f"(e.z), "f"(e.w)
                         : "memory");
        }
    }
}

// ---------------------------------------------------------------------------
extern "C" void kernel_launch(void* const* d_in, const int* in_sizes, int n_in,
                              void* d_out, int out_size)
{
    const float* obj   = (const float*)d_in[0];
    const float* waves = (const float*)d_in[1];
    const int*   pos   = (const int*)d_in[2];

    float* patches = (float*)d_out;
    float* norm    = (float*)d_out + PATCHES_ELEMS;

    bc_zero_norm<<<NORM_ELEMS / 4 / 256, 256>>>((float4*)norm);

    bc_main<<<PERSIST_GRID, 256>>>(
        obj, (const float4*)waves, pos, (float4*)patches, norm);
}

// round 16
// speedup vs baseline: 1.1498x; 1.1498x over previous
#include <cuda_runtime.h>
#include <cstdint>

#define N_MODES 4
#define BATCH   1024
#define PH      128
#define PW      128
#define OBJ_H   2048
#define OBJ_W   2048

#define PATCHES_ELEMS (BATCH * PH * PW)   // 16,777,216
#define NORM_ELEMS    (OBJ_H * OBJ_W)     // 4,194,304

// ---------------------------------------------------------------------------
// Kernel 1: zero object_norm. Best measured config: 4096 blocks x 256
// threads, one coalesced float4 store per thread.
// ---------------------------------------------------------------------------
__global__ void __launch_bounds__(256) bc_zero_norm(float4* __restrict__ norm4) {
    int i = blockIdx.x * 256 + threadIdx.x;            // NORM_ELEMS/4 threads
    norm4[i] = make_float4(0.f, 0.f, 0.f, 0.f);
}

// ---------------------------------------------------------------------------
// Kernel 2: fused patch-norm + aligned scatter-add + aligned batch-crop.
// FINAL configuration (best measured: 57.824 us total, reproduced twice;
// bc_main 51.5 us at 83% DRAM SOL — its stream-traffic floor of ~338 MB).
//   block = 256 threads = 8 warps; each warp owns one full 128-float row.
//   grid  = BATCH * (PH/8) = 16384 independent short blocks.
//   - waves read + patches write use streaming policy (__ldcs/__stcs) so the
//     reused obj + norm working set (~32 MB) stays L2-resident.
//   - pc%4 misalignment handled entirely with intra-warp shuffles: obj is
//     loaded as aligned LDG.128 and realigned; patch_norm is de-aligned and
//     scattered with aligned red.global.add.v4.f32 (4x fewer L2 atomic ops).
//   - no shared memory, no barriers.
// ---------------------------------------------------------------------------
__global__ void __launch_bounds__(256) bc_main(
    const float*  __restrict__ obj,
    const float4* __restrict__ waves4,
    const int*    __restrict__ pos,
    float4*       __restrict__ patches4,
    float*        __restrict__ norm)
{
    const int bid = blockIdx.x;
    const int b   = bid >> 4;             // patch index
    const int h0  = (bid & 15) << 3;      // first row of this 8-row chunk
    const int t   = threadIdx.x;
    const int r   = t >> 5;               // warp id = row within chunk
    const int g   = t & 31;               // lane = float4 group within row
    const int h   = h0 + r;

    const int pr = __ldg(&pos[2 * b]);
    const int pc = __ldg(&pos[2 * b + 1]);
    const int s  = pc & 3;                // misalignment (uniform per block)
    const int A  = pc - s;                // 16B-aligned start column

    // ---- patch_norm = sum over 4 modes of waves^2 (streaming float4) ----
    const size_t MS   = (size_t)BATCH * PH * (PW / 4);
    const size_t pidx = ((size_t)b * PH + h) * (PW / 4) + g;

    float4 a0 = __ldcs(&waves4[pidx]);
    float4 a1 = __ldcs(&waves4[pidx + MS]);
    float4 a2 = __ldcs(&waves4[pidx + 2 * MS]);
    float4 a3 = __ldcs(&waves4[pidx + 3 * MS]);

    float4 nv;
    nv.x = a0.x*a0.x + a1.x*a1.x + a2.x*a2.x + a3.x*a3.x;
    nv.y = a0.y*a0.y + a1.y*a1.y + a2.y*a2.y + a3.y*a3.y;
    nv.z = a0.z*a0.z + a1.z*a1.z + a2.z*a2.z + a3.z*a3.z;
    nv.w = a0.w*a0.w + a1.w*a1.w + a2.w*a2.w + a3.w*a3.w;

    // ---- obj gather: ALIGNED float4 loads + shuffle realign ----
    const float4* orow4 = (const float4*)(obj + (size_t)(pr + h) * OBJ_W + A);
    float4 L = __ldg(&orow4[g]);
    float4 E = make_float4(0.f, 0.f, 0.f, 0.f);
    if (s && g == 31) E = __ldg(&orow4[32]);   // pc <= 1919 -> always in-row

    float4 nxt;
    nxt.x = __shfl_down_sync(0xffffffffu, L.x, 1);
    nxt.y = __shfl_down_sync(0xffffffffu, L.y, 1);
    nxt.z = __shfl_down_sync(0xffffffffu, L.z, 1);
    nxt.w = __shfl_down_sync(0xffffffffu, L.w, 1);
    if (g == 31) nxt = E;

    float4 v;
    switch (s) {            // uniform branch (same s for whole block)
        case 0:  v = L; break;
        case 1:  v = make_float4(L.y, L.z, L.w, nxt.x); break;
        case 2:  v = make_float4(L.z, L.w, nxt.x, nxt.y); break;
        default: v = make_float4(L.w, nxt.x, nxt.y, nxt.z); break;
    }
    __stcs(&patches4[pidx], v);

    // ---- norm scatter: shuffle de-align + ALIGNED red.global.add.v4 ----
    float4 prev;
    prev.x = __shfl_up_sync(0xffffffffu, nv.x, 1);
    prev.y = __shfl_up_sync(0xffffffffu, nv.y, 1);
    prev.z = __shfl_up_sync(0xffffffffu, nv.z, 1);
    prev.w = __shfl_up_sync(0xffffffffu, nv.w, 1);
    if (g == 0) prev = make_float4(0.f, 0.f, 0.f, 0.f);

    float4 o;
    switch (s) {
        case 0:  o = nv; break;
        case 1:  o = make_float4(prev.w, nv.x, nv.y, nv.z); break;
        case 2:  o = make_float4(prev.z, prev.w, nv.x, nv.y); break;
        default: o = make_float4(prev.y, prev.z, prev.w, nv.x); break;
    }

    float* nrow = norm + (size_t)(pr + h) * OBJ_W;
    asm volatile("red.global.add.v4.f32 [%0], {%1, %2, %3, %4};"
                 :: "l"(nrow + A + 4 * g), "f"(o.x), "f"(o.y), "f"(o.z), "f"(o.w)
                 : "memory");

    // Extra aligned group (columns A+128..A+131) carries the last s elements.
    if (s && g == 31) {
        float4 e;
        switch (s) {
            case 1:  e = make_float4(nv.w, 0.f, 0.f, 0.f); break;
            case 2:  e = make_float4(nv.z, nv.w, 0.f, 0.f); break;
            default: e = make_float4(nv.y, nv.z, nv.w, 0.f); break;
        }
        asm volatile("red.global.add.v4.f32 [%0], {%1, %2, %3, %4};"
                     :: "l"(nrow + A + 128), "f"(e.x), "f"(e.y), "f"(e.z), "f"(e.w)
                     : "memory");
    }
}

// ---------------------------------------------------------------------------
extern "C" void kernel_launch(void* const* d_in, const int* in_sizes, int n_in,
                              void* d_out, int out_size)
{
    const float* obj   = (const float*)d_in[0];
    const float* waves = (const float*)d_in[1];
    const int*   pos   = (const int*)d_in[2];

    float* patches = (float*)d_out;
    float* norm    = (float*)d_out + PATCHES_ELEMS;

    bc_zero_norm<<<NORM_ELEMS / 4 / 256, 256>>>((float4*)norm);

    bc_main<<<BATCH * (PH / 8), 256>>>(
        obj, (const float4*)waves, pos, (float4*)patches, norm);
}

// round 17
// speedup vs baseline: 1.1765x; 1.0232x over previous
#include <cuda_runtime.h>
#include <cstdint>

#define N_MODES 4
#define BATCH   1024
#define PH      128
#define PW      128
#define OBJ_H   2048
#define OBJ_W   2048

#define PATCHES_ELEMS (BATCH * PH * PW)   // 16,777,216
#define NORM_ELEMS    (OBJ_H * OBJ_W)     // 4,194,304

// ---------------------------------------------------------------------------
// Kernel 1: zero object_norm. Best measured config: 4096 blocks x 256
// threads, one coalesced float4 store per thread.
// ---------------------------------------------------------------------------
__global__ void __launch_bounds__(256) bc_zero_norm(float4* __restrict__ norm4) {
    int i = blockIdx.x * 256 + threadIdx.x;            // NORM_ELEMS/4 threads
    norm4[i] = make_float4(0.f, 0.f, 0.f, 0.f);
}

// ---------------------------------------------------------------------------
// Kernel 2: fused patch-norm + aligned scatter-add + aligned batch-crop.
// FINAL configuration (best measured: 57.824 us total, reproduced twice;
// bc_main 51.5 us at 83% DRAM SOL — its stream-traffic floor of ~338 MB).
//   block = 256 threads = 8 warps; each warp owns one full 128-float row.
//   grid  = BATCH * (PH/8) = 16384 independent short blocks.
//   - waves read + patches write use streaming policy (__ldcs/__stcs) so the
//     reused obj + norm working set (~32 MB) stays L2-resident.
//   - pc%4 misalignment handled entirely with intra-warp shuffles: obj is
//     loaded as aligned LDG.128 and realigned; patch_norm is de-aligned and
//     scattered with aligned red.global.add.v4.f32 (4x fewer L2 atomic ops).
//   - no shared memory, no barriers.
// ---------------------------------------------------------------------------
__global__ void __launch_bounds__(256) bc_main(
    const float*  __restrict__ obj,
    const float4* __restrict__ waves4,
    const int*    __restrict__ pos,
    float4*       __restrict__ patches4,
    float*        __restrict__ norm)
{
    const int bid = blockIdx.x;
    const int b   = bid >> 4;             // patch index
    const int h0  = (bid & 15) << 3;      // first row of this 8-row chunk
    const int t   = threadIdx.x;
    const int r   = t >> 5;               // warp id = row within chunk
    const int g   = t & 31;               // lane = float4 group within row
    const int h   = h0 + r;

    const int pr = __ldg(&pos[2 * b]);
    const int pc = __ldg(&pos[2 * b + 1]);
    const int s  = pc & 3;                // misalignment (uniform per block)
    const int A  = pc - s;                // 16B-aligned start column

    // ---- patch_norm = sum over 4 modes of waves^2 (streaming float4) ----
    const size_t MS   = (size_t)BATCH * PH * (PW / 4);
    const size_t pidx = ((size_t)b * PH + h) * (PW / 4) + g;

    float4 a0 = __ldcs(&waves4[pidx]);
    float4 a1 = __ldcs(&waves4[pidx + MS]);
    float4 a2 = __ldcs(&waves4[pidx + 2 * MS]);
    float4 a3 = __ldcs(&waves4[pidx + 3 * MS]);

    float4 nv;
    nv.x = a0.x*a0.x + a1.x*a1.x + a2.x*a2.x + a3.x*a3.x;
    nv.y = a0.y*a0.y + a1.y*a1.y + a2.y*a2.y + a3.y*a3.y;
    nv.z = a0.z*a0.z + a1.z*a1.z + a2.z*a2.z + a3.z*a3.z;
    nv.w = a0.w*a0.w + a1.w*a1.w + a2.w*a2.w + a3.w*a3.w;

    // ---- obj gather: ALIGNED float4 loads + shuffle realign ----
    const float4* orow4 = (const float4*)(obj + (size_t)(pr + h) * OBJ_W + A);
    float4 L = __ldg(&orow4[g]);
    float4 E = make_float4(0.f, 0.f, 0.f, 0.f);
    if (s && g == 31) E = __ldg(&orow4[32]);   // pc <= 1919 -> always in-row

    float4 nxt;
    nxt.x = __shfl_down_sync(0xffffffffu, L.x, 1);
    nxt.y = __shfl_down_sync(0xffffffffu, L.y, 1);
    nxt.z = __shfl_down_sync(0xffffffffu, L.z, 1);
    nxt.w = __shfl_down_sync(0xffffffffu, L.w, 1);
    if (g == 31) nxt = E;

    float4 v;
    switch (s) {            // uniform branch (same s for whole block)
        case 0:  v = L; break;
        case 1:  v = make_float4(L.y, L.z, L.w, nxt.x); break;
        case 2:  v = make_float4(L.z, L.w, nxt.x, nxt.y); break;
        default: v = make_float4(L.w, nxt.x, nxt.y, nxt.z); break;
    }
    __stcs(&patches4[pidx], v);

    // ---- norm scatter: shuffle de-align + ALIGNED red.global.add.v4 ----
    float4 prev;
    prev.x = __shfl_up_sync(0xffffffffu, nv.x, 1);
    prev.y = __shfl_up_sync(0xffffffffu, nv.y, 1);
    prev.z = __shfl_up_sync(0xffffffffu, nv.z, 1);
    prev.w = __shfl_up_sync(0xffffffffu, nv.w, 1);
    if (g == 0) prev = make_float4(0.f, 0.f, 0.f, 0.f);

    float4 o;
    switch (s) {
        case 0:  o = nv; break;
        case 1:  o = make_float4(prev.w, nv.x, nv.y, nv.z); break;
        case 2:  o = make_float4(prev.z, prev.w, nv.x, nv.y); break;
        default: o = make_float4(prev.y, prev.z, prev.w, nv.x); break;
    }

    float* nrow = norm + (size_t)(pr + h) * OBJ_W;
    asm volatile("red.global.add.v4.f32 [%0], {%1, %2, %3, %4};"
                 :: "l"(nrow + A + 4 * g), "f"(o.x), "f"(o.y), "f"(o.z), "f"(o.w)
                 : "memory");

    // Extra aligned group (columns A+128..A+131) carries the last s elements.
    if (s && g == 31) {
        float4 e;
        switch (s) {
            case 1:  e = make_float4(nv.w, 0.f, 0.f, 0.f); break;
            case 2:  e = make_float4(nv.z, nv.w, 0.f, 0.f); break;
            default: e = make_float4(nv.y, nv.z, nv.w, 0.f); break;
        }
        asm volatile("red.global.add.v4.f32 [%0], {%1, %2, %3, %4};"
                     :: "l"(nrow + A + 128), "f"(e.x), "f"(e.y), "f"(e.z), "f"(e.w)
                     : "memory");
    }
}

// ---------------------------------------------------------------------------
extern "C" void kernel_launch(void* const* d_in, const int* in_sizes, int n_in,
                              void* d_out, int out_size)
{
    const float* obj   = (const float*)d_in[0];
    const float* waves = (const float*)d_in[1];
    const int*   pos   = (const int*)d_in[2];

    float* patches = (float*)d_out;
    float* norm    = (float*)d_out + PATCHES_ELEMS;

    bc_zero_norm<<<NORM_ELEMS / 4 / 256, 256>>>((float4*)norm);

    bc_main<<<BATCH * (PH / 8), 256>>>(
        obj, (const float4*)waves, pos, (float4*)patches, norm);
}